// round 1
// baseline (speedup 1.0000x reference)
#include <cuda_runtime.h>

// PCEN: s[t] = (1-c)*x[t] + c*s[t-1];  y = (x * (eps+s)^-alpha + delta)^root - delta^root
// x: [B=64, T=2048, F=128, C=1] fp32. Chunked-in-T single kernel exploiting the
// exponentially short memory of the IIR (warm-up length derived from c at runtime;
// exact fallback to scan-from-0 when c -> 1).

#define B_DIM 64
#define T_DIM 2048
#define F_DIM 128
#define CT    128                 // timesteps per chunk
#define NCHUNK (T_DIM / CT)       // 16
#define EPS_F 1e-6f

__device__ __forceinline__ float lg2_approx(float x) {
    float r; asm("lg2.approx.f32 %0, %1;" : "=f"(r) : "f"(x)); return r;
}
__device__ __forceinline__ float ex2_approx(float x) {
    float r; asm("ex2.approx.f32 %0, %1;" : "=f"(r) : "f"(x)); return r;
}
__device__ __forceinline__ float sqrt_approx(float x) {
    float r; asm("sqrt.approx.f32 %0, %1;" : "=f"(r) : "f"(x)); return r;
}

__global__ __launch_bounds__(F_DIM, 8)
void pcen_kernel(const float* __restrict__ x,
                 const float* __restrict__ alpha_p,
                 const float* __restrict__ delta_p,
                 const float* __restrict__ root_p,
                 const float* __restrict__ c_p,
                 float* __restrict__ y)
{
    const int f  = threadIdx.x;          // 0..127, contiguous -> coalesced
    const int b  = blockIdx.y;           // 0..63
    const int t0 = blockIdx.x * CT;      // chunk start

    const float c     = __ldg(c_p);
    const float omc   = 1.0f - c;
    const float alpha = __ldg(alpha_p);
    const float delta = __ldg(delta_p);
    const float root  = __ldg(root_p);
    const bool  half_root = (root == 0.5f);
    const float droot = half_root ? sqrt_approx(delta)
                                  : ex2_approx(root * lg2_approx(delta));
    const float nalpha = -alpha;

    // Warm-up length: smallest W with c^W <= 2^-46 (then truncation error is
    // ~1e-14 relative). If c >= ~1 (or lg2(c) ~ 0), scan exactly from t=0.
    int W;
    if (c <= 0.0f) {
        W = 0;
    } else {
        float l2c = lg2_approx(c);
        if (l2c >= -1e-6f) {
            W = t0;                       // exact fallback
        } else {
            float w = -46.0f / l2c;
            W = (w >= (float)t0) ? t0 : ((int)w + 1);
        }
    }
    const int tstart = t0 - W;

    const size_t base = ((size_t)b * T_DIM) * F_DIM + (size_t)f;
    const float* __restrict__ px = x + base;
    float*       __restrict__ py = y + base;

    float s = 0.0f;

    // Warm-up: EMA only, no output.
    for (int t = tstart; t < t0; ++t) {
        s = fmaf(c, s, omc * __ldg(px + (size_t)t * F_DIM));
    }

    // Main chunk: EMA + PCEN pointwise, fully coalesced loads/stores.
    #pragma unroll 4
    for (int i = 0; i < CT; ++i) {
        const size_t off = (size_t)(t0 + i) * F_DIM;
        const float xv = __ldg(px + off);
        s = fmaf(c, s, omc * xv);
        const float m = EPS_F + s;
        // (eps+s)^-alpha via ex2/lg2 (no division)
        const float r = ex2_approx(nalpha * lg2_approx(m));
        const float u = fmaf(xv, r, delta);
        const float o = half_root ? sqrt_approx(u)
                                  : ex2_approx(root * lg2_approx(u));
        py[off] = o - droot;
    }
}

extern "C" void kernel_launch(void* const* d_in, const int* in_sizes, int n_in,
                              void* d_out, int out_size)
{
    const float* x       = (const float*)d_in[0];
    const float* alpha_p = (const float*)d_in[1];
    const float* delta_p = (const float*)d_in[2];
    const float* root_p  = (const float*)d_in[3];
    const float* coef_p  = (const float*)d_in[4];
    float* y = (float*)d_out;

    dim3 grid(NCHUNK, B_DIM, 1);   // (16, 64)
    dim3 block(F_DIM, 1, 1);       // 128
    pcen_kernel<<<grid, block>>>(x, alpha_p, delta_p, root_p, coef_p, y);
}